// round 10
// baseline (speedup 1.0000x reference)
#include <cuda_runtime.h>
#include <cuda_bf16.h>
#include <stdint.h>

#define NHD 12
#define HSD 64
#define HD  768
#define BD  16
#define SD  512
#define BH  (BD*NHD)        /* 192  */
#define MROWS (BD*SD)       /* 8192 */
#define SCALE 0.125f
#define TAU 3e-4f
#define FIX_CAP (1u<<20)

#define CTX_ELEMS   ((size_t)BD*SD*HD)        /* 6291456  */
#define SCORE_ELEMS ((size_t)BD*NHD*SD*SD)    /* 50331648 */
#define OFF_CTX  ((size_t)0)
#define OFF_ATTN (CTX_ELEMS)
#define OFF_VAL  (OFF_ATTN + SCORE_ELEMS)
#define OFF_QRY  (OFF_VAL  + SCORE_ELEMS)
#define OFF_KEY  (OFF_QRY  + SCORE_ELEMS)

// ---- warp-MMA + async-copy helpers (baseline PTX, compute_103-safe) ---------
__device__ __forceinline__ uint32_t smem_u32(const void* p) {
    uint32_t a;
    asm("{ .reg .u64 t; cvta.to.shared.u64 t, %1; cvt.u32.u64 %0, t; }" : "=r"(a) : "l"(p));
    return a;
}
#define SW128(off) ((off) ^ (((off) >> 3) & 0x70))

__device__ __forceinline__ void ldsm_x4(uint32_t& r0, uint32_t& r1, uint32_t& r2,
                                        uint32_t& r3, uint32_t addr) {
    asm volatile("ldmatrix.sync.aligned.m8n8.x4.shared.b16 {%0,%1,%2,%3}, [%4];"
                 : "=r"(r0), "=r"(r1), "=r"(r2), "=r"(r3) : "r"(addr));
}
__device__ __forceinline__ void mma_16816(float* c, const uint32_t* a, uint32_t b0, uint32_t b1) {
    asm volatile(
        "mma.sync.aligned.m16n8k16.row.col.f32.bf16.bf16.f32 "
        "{%0,%1,%2,%3}, {%4,%5,%6,%7}, {%8,%9}, {%0,%1,%2,%3};"
        : "+f"(c[0]), "+f"(c[1]), "+f"(c[2]), "+f"(c[3])
        : "r"(a[0]), "r"(a[1]), "r"(a[2]), "r"(a[3]), "r"(b0), "r"(b1));
}
__device__ __forceinline__ void cp_async16(uint32_t dst, const void* src) {
    unsigned long long g;
    asm("cvta.to.global.u64 %0, %1;" : "=l"(g) : "l"(src));
    asm volatile("cp.async.cg.shared.global [%0], [%1], 16;" :: "r"(dst), "l"(g) : "memory");
}
#define CP_COMMIT() asm volatile("cp.async.commit_group;" ::: "memory")
#define CP_WAIT(n)  asm volatile("cp.async.wait_group %0;" :: "n"(n) : "memory")

// ---------------- scratch (static __device__, no allocation) ----------------
__device__ float d_Q[MROWS*HD];
__device__ float d_K[MROWS*HD];
__device__ float d_V[MROWS*HD];
__device__ float d_scales[3*HD];
__device__ __nv_bfloat16 d_Xh[MROWS*HD];
__device__ __nv_bfloat16 d_Xl[MROWS*HD];
__device__ __nv_bfloat16 d_Wh[3*HD*HD];
__device__ __nv_bfloat16 d_Wl[3*HD*HD];
__device__ __nv_bfloat16 d_Ph[3*(size_t)MROWS*HD];   // bf16 hi of Q/K/V
__device__ __nv_bfloat16 d_Pl[3*(size_t)MROWS*HD];   // bf16 lo of Q/K/V
__device__ unsigned d_fix_cnt;
__device__ unsigned d_fix_idx[FIX_CAP];
__device__ unsigned long long d_qb[BH*SD];
__device__ unsigned long long d_kb[BH*SD];
__device__ unsigned long long d_vt[BH*HSD*8];

// ---------------- 1) per-row weight scales (rounding-critical) ---------------
__global__ void scale_kernel(const float* __restrict__ Wq,
                             const float* __restrict__ Wk,
                             const float* __restrict__ Wv) {
    if (blockIdx.x == 0 && blockIdx.y == 0 && threadIdx.x == 0) d_fix_cnt = 0;
    int row = blockIdx.x;
    int which = blockIdx.y;
    const float* W = (which == 0) ? Wq : (which == 1) ? Wk : Wv;
    int lane = threadIdx.x;
    float s = 0.f;
#pragma unroll
    for (int i = 0; i < 24; i++)
        s += fabsf(W[(size_t)row*HD + lane + 32*i]);
#pragma unroll
    for (int o = 16; o > 0; o >>= 1)
        s += __shfl_down_sync(0xffffffffu, s, o);
    if (lane == 0) d_scales[which*HD + row] = s / 768.0f;
}

// ---------------- 2a) split X into bf16 hi/lo --------------------------------
__global__ void xsplit_kernel(const float* __restrict__ X) {
    size_t i = ((size_t)blockIdx.x * 256 + threadIdx.x) * 4;
    float4 x = *(const float4*)&X[i];
    __nv_bfloat162 h0 = __floats2bfloat162_rn(x.x, x.y);
    __nv_bfloat162 h1 = __floats2bfloat162_rn(x.z, x.w);
    __nv_bfloat162 l0 = __floats2bfloat162_rn(x.x - __bfloat162float(h0.x),
                                              x.y - __bfloat162float(h0.y));
    __nv_bfloat162 l1 = __floats2bfloat162_rn(x.z - __bfloat162float(h1.x),
                                              x.w - __bfloat162float(h1.y));
    *(uint2*)&d_Xh[i] = make_uint2(*(uint32_t*)&h0, *(uint32_t*)&h1);
    *(uint2*)&d_Xl[i] = make_uint2(*(uint32_t*)&l0, *(uint32_t*)&l1);
}

// ---------------- 2b) quantize weights to +-s_j, split into bf16 hi/lo -------
__global__ void wsplit_kernel(const float* __restrict__ Wq,
                              const float* __restrict__ Wk,
                              const float* __restrict__ Wv) {
    int which = blockIdx.y;
    const float* W = (which == 0) ? Wq : (which == 1) ? Wk : Wv;
    size_t i = ((size_t)blockIdx.x * 256 + threadIdx.x) * 4;
    int row = (int)(i / HD);
    float s = d_scales[which*HD + row];
    __nv_bfloat16 sh = __float2bfloat16_rn(s);
    __nv_bfloat16 sl = __float2bfloat16_rn(s - __bfloat162float(sh));
    float4 w = *(const float4*)&W[i];
    __nv_bfloat16 zero = __float2bfloat16_rn(0.f);
    __nv_bfloat16 h[4], l[4];
    float wf[4] = {w.x, w.y, w.z, w.w};
#pragma unroll
    for (int j = 0; j < 4; j++) {
        if (wf[j] > 0.f)      { h[j] = sh;  l[j] = sl;  }
        else if (wf[j] < 0.f) { h[j] = __hneg(sh); l[j] = __hneg(sl); }
        else                  { h[j] = zero; l[j] = zero; }
    }
    size_t o = (size_t)which*HD*HD + i;
    *(uint2*)&d_Wh[o] = *(uint2*)h;
    *(uint2*)&d_Wl[o] = *(uint2*)l;
}

// ---------------- 2c) projection GEMM: cp.async pipelined warp-MMA -----------
// 512 threads, 4x4 warps of 32x32 tiles, double-buffered 64KB stages.
#define PJ_BUF 65536
#define PJ_SMEM 131072

__global__ __launch_bounds__(512, 1)
void proj_mma_kernel(const float* __restrict__ bq, const float* __restrict__ bk,
                     const float* __restrict__ bv) {
    extern __shared__ char smc[];
    uint32_t sbase = smem_u32(smc);
    int tid = threadIdx.x;
    int wid = tid / 32, lane = tid % 32;

    int bn = blockIdx.x;
    int which = bn / 6;
    int j0 = (bn % 6) * 128;
    int m0 = blockIdx.y * 128;
    const float* bias = (which == 0) ? bq : (which == 1) ? bk : bv;
    float* dst        = (which == 0) ? d_Q : (which == 1) ? d_K : d_V;
    __nv_bfloat16* ph = d_Ph + (size_t)which*MROWS*HD;
    __nv_bfloat16* pl = d_Pl + (size_t)which*MROWS*HD;

    // loader role: tile 0=AH 1=AL 2=BH 3=BL, one 128B row each
    int ltile = tid >> 7, lrow = tid & 127;
    const __nv_bfloat16* gbase;
    if      (ltile == 0) gbase = d_Xh + (size_t)(m0 + lrow)*HD;
    else if (ltile == 1) gbase = d_Xl + (size_t)(m0 + lrow)*HD;
    else if (ltile == 2) gbase = d_Wh + ((size_t)which*HD + j0 + lrow)*HD;
    else                 gbase = d_Wl + ((size_t)which*HD + j0 + lrow)*HD;
    uint32_t sdoff = (uint32_t)ltile*16384;
    uint32_t lsw[8];
#pragma unroll
    for (int j = 0; j < 8; j++) lsw[j] = SW128((uint32_t)lrow*128 + j*16);

    int wm = wid >> 2, wn = wid & 3;
    int r8   = (lane & 7) + 8*((lane >> 3) & 1);
    int cb16 = 16 * (lane >> 4);

    float acc[2][4][4];
#pragma unroll
    for (int mg = 0; mg < 2; mg++)
#pragma unroll
        for (int ng = 0; ng < 4; ng++)
#pragma unroll
            for (int c = 0; c < 4; c++) acc[mg][ng][c] = 0.f;

    // preload k-tile 0
    {
        uint32_t d0 = sbase + sdoff;
#pragma unroll
        for (int j = 0; j < 8; j++) cp_async16(d0 + lsw[j], gbase + j*8);
        CP_COMMIT();
    }

    for (int kt = 0; kt < 12; kt++) {
        if (kt < 11) {
            const __nv_bfloat16* g = gbase + (kt+1)*64;
            uint32_t d0 = sbase + (uint32_t)((kt+1)&1)*PJ_BUF + sdoff;
#pragma unroll
            for (int j = 0; j < 8; j++) cp_async16(d0 + lsw[j], g + j*8);
            CP_COMMIT();
            CP_WAIT(1);
        } else {
            CP_WAIT(0);
        }
        __syncthreads();
        uint32_t bufb = sbase + (uint32_t)(kt&1)*PJ_BUF;
#pragma unroll
        for (int p = 0; p < 3; p++) {
            uint32_t aoff = bufb + ((p == 2) ? 16384u : 0u);
            uint32_t boff = bufb + 32768u + ((p == 1) ? 16384u : 0u);
#pragma unroll
            for (int k0 = 0; k0 < 4; k0++) {
                uint32_t kb = (uint32_t)k0*32 + cb16;
                uint32_t a[2][4];
#pragma unroll
                for (int mg = 0; mg < 2; mg++)
                    ldsm_x4(a[mg][0], a[mg][1], a[mg][2], a[mg][3],
                            aoff + SW128((uint32_t)(wm*32 + mg*16 + r8)*128 + kb));
                uint32_t bf[8];
#pragma unroll
                for (int bg = 0; bg < 2; bg++) {
                    uint32_t r0, r1, r2, r3;
                    ldsm_x4(r0, r1, r2, r3,
                            boff + SW128((uint32_t)(wn*32 + bg*16 + r8)*128 + kb));
                    bf[4*bg + 0] = r0; bf[4*bg + 1] = r2;
                    bf[4*bg + 2] = r1; bf[4*bg + 3] = r3;
                }
#pragma unroll
                for (int mg = 0; mg < 2; mg++)
#pragma unroll
                    for (int ng = 0; ng < 4; ng++)
                        mma_16816(acc[mg][ng], a[mg], bf[2*ng], bf[2*ng + 1]);
            }
        }
        __syncthreads();
    }

    // epilogue: bias, fp32 write, bf16 hi/lo write, near-zero flags
    unsigned wbase = (unsigned)which * (unsigned)(MROWS*HD);
#pragma unroll
    for (int mg = 0; mg < 2; mg++) {
        int row = m0 + wm*32 + mg*16 + (lane >> 2);
#pragma unroll
        for (int ng = 0; ng < 4; ng++) {
            int col = j0 + wn*32 + ng*8 + 2*(lane & 3);
            float b0 = bias[col], b1 = bias[col+1];
            float v[2][2] = {{acc[mg][ng][0] + b0, acc[mg][ng][1] + b1},
                             {acc[mg][ng][2] + b0, acc[mg][ng][3] + b1}};
#pragma unroll
            for (int rr = 0; rr < 2; rr++) {
                int r = row + rr*8;
                size_t o = (size_t)r*HD + col;
                *(float2*)&dst[o] = make_float2(v[rr][0], v[rr][1]);
                __nv_bfloat162 hh, ll;
                hh = __floats2bfloat162_rn(v[rr][0], v[rr][1]);
                ll = __floats2bfloat162_rn(v[rr][0] - __bfloat162float(hh.x),
                                           v[rr][1] - __bfloat162float(hh.y));
                *(uint32_t*)&ph[o] = *(uint32_t*)&hh;
                *(uint32_t*)&pl[o] = *(uint32_t*)&ll;
                if (fabsf(v[rr][0]) < TAU) {
                    unsigned p = atomicAdd(&d_fix_cnt, 1u);
                    if (p < FIX_CAP) d_fix_idx[p] = wbase + (unsigned)o;
                }
                if (fabsf(v[rr][1]) < TAU) {
                    unsigned p = atomicAdd(&d_fix_cnt, 1u);
                    if (p < FIX_CAP) d_fix_idx[p] = wbase + (unsigned)o + 1;
                }
            }
        }
    }
}

// ---------------- 2d) exact fixup: serial FMA chain (matches reference) ------
__global__ void fix_kernel(const float* __restrict__ X,
                           const float* __restrict__ Wq, const float* __restrict__ Wk,
                           const float* __restrict__ Wv,
                           const float* __restrict__ bq, const float* __restrict__ bk,
                           const float* __restrict__ bv) {
    unsigned cnt = d_fix_cnt;
    if (cnt > FIX_CAP) cnt = FIX_CAP;
    for (unsigned i = blockIdx.x * blockDim.x + threadIdx.x; i < cnt;
         i += gridDim.x * blockDim.x) {
        unsigned idx = d_fix_idx[i];
        int which = idx / (MROWS*HD);
        unsigned rem = idx - (unsigned)which * (MROWS*HD);
        int m = rem / HD, j = rem % HD;
        const float* W    = (which == 0) ? Wq : (which == 1) ? Wk : Wv;
        const float* bias = (which == 0) ? bq : (which == 1) ? bk : bv;
        float* dst        = (which == 0) ? d_Q : (which == 1) ? d_K : d_V;
        float s = d_scales[which*HD + j];
        const float* xr = X + (size_t)m*HD;
        const float* wr = W + (size_t)j*HD;
        float acc = 0.f;
        for (int k = 0; k < HD; k++) {
            float w = wr[k];
            float b = (w > 0.f) ? s : ((w < 0.f) ? -s : 0.f);
            acc = fmaf(xr[k], b, acc);
        }
        float v = acc + bias[j];
        size_t o = (size_t)m*HD + j;
        dst[o] = v;
        __nv_bfloat16 hh = __float2bfloat16_rn(v);
        d_Ph[(size_t)which*MROWS*HD + o] = hh;
        d_Pl[(size_t)which*MROWS*HD + o] =
            __float2bfloat16_rn(v - __bfloat162float(hh));
    }
}

// ---------------- 3) pack sign bits of Q,K along head dim --------------------
__global__ void pack_qk_kernel() {
    int tid = threadIdx.x;
    int warp = tid / 32, lane = tid % 32;
    int idx = blockIdx.x * 8 + warp;
    int tensor = (idx >= BH*SD) ? 1 : 0;
    int r = idx - tensor * (BH*SD);
    int bh = r / SD, s = r % SD;
    int b = bh / NHD, h = bh % NHD;
    const float* src = tensor ? d_K : d_Q;
    size_t base = ((size_t)(b*SD + s))*HD + h*HSD;
    float x0 = src[base + lane];
    float x1 = src[base + 32 + lane];
    unsigned lo = __ballot_sync(0xffffffffu, x0 > 0.f);
    unsigned hi = __ballot_sync(0xffffffffu, x1 > 0.f);
    if (lane == 0) {
        unsigned long long bits = (unsigned long long)lo | ((unsigned long long)hi << 32);
        if (tensor) d_kb[(size_t)bh*SD + s] = bits;
        else        d_qb[(size_t)bh*SD + s] = bits;
    }
}

// ---------------- 4) pack sign bits of V transposed --------------------------
__global__ void pack_vt_kernel() {
    __shared__ float sv[64][68];
    int tid = threadIdx.x;
    int w  = blockIdx.x;
    int bh = blockIdx.y;
    int b = bh / NHD, h = bh % NHD;
    int row = tid / 4;
    int c0  = (tid % 4) * 16;
    const float* base = d_V + ((size_t)(b*SD + w*64 + row))*HD + h*HSD;
#pragma unroll
    for (int i = 0; i < 4; i++) {
        float4 v = *(const float4*)(base + c0 + 4*i);
        sv[row][c0 + 4*i + 0] = v.x; sv[row][c0 + 4*i + 1] = v.y;
        sv[row][c0 + 4*i + 2] = v.z; sv[row][c0 + 4*i + 3] = v.w;
    }
    __syncthreads();
    int warp = tid / 32, lane = tid % 32;
#pragma unroll
    for (int it = 0; it < 8; it++) {
        int d = warp * 8 + it;
        unsigned lo = __ballot_sync(0xffffffffu, sv[lane][d]      > 0.f);
        unsigned hi = __ballot_sync(0xffffffffu, sv[lane + 32][d] > 0.f);
        if (lane == 0)
            d_vt[((size_t)bh*HSD + d)*8 + w] =
                (unsigned long long)lo | ((unsigned long long)hi << 32);
    }
}

// ---------------- 5) score GEMMs: cp.async + warp-MMA on pre-split bf16 ------
#define SC_SMEM 65536

__global__ __launch_bounds__(512, 1)
void score_mma_kernel(float* __restrict__ out) {
    extern __shared__ char smc[];
    uint32_t sbase = smem_u32(smc);
    int tid = threadIdx.x;
    int wid = tid / 32, lane = tid % 32;

    int bh = blockIdx.y, z = blockIdx.z;
    int qt = blockIdx.x >> 2, kt = blockIdx.x & 3;
    int b = bh / NHD, h = bh % NHD;
    const __nv_bfloat16* srcH = d_Ph + (size_t)z*MROWS*HD;
    const __nv_bfloat16* srcL = d_Pl + (size_t)z*MROWS*HD;
    size_t off = (z == 0) ? OFF_QRY : (z == 1) ? OFF_KEY : OFF_VAL;

    // load: tile 0=AH(qt) 1=AL(qt) 2=BH(kt) 3=BL(kt); one 128B row each thread
    {
        int ltile = tid >> 7, lrow = tid & 127;
        int rt = (ltile < 2) ? qt : kt;
        const __nv_bfloat16* gsrc = (ltile & 1) ? srcL : srcH;
        const __nv_bfloat16* g = gsrc + ((size_t)(b*SD + rt*128 + lrow))*HD + h*HSD;
        uint32_t d0 = sbase + (uint32_t)ltile*16384;
#pragma unroll
        for (int j = 0; j < 8; j++)
            cp_async16(d0 + SW128((uint32_t)lrow*128 + j*16), g + j*8);
        CP_COMMIT();
    }
    CP_WAIT(0);
    __syncthreads();

    int wm = wid >> 2, wn = wid & 3;
    int r8   = (lane & 7) + 8*((lane >> 3) & 1);
    int cb16 = 16 * (lane >> 4);

    float acc[2][4][4];
#pragma unroll
    for (int mg = 0; mg < 2; mg++)
#pragma unroll
        for (int ng = 0; ng < 4; ng++)
#pragma unroll
            for (int c = 0; c < 4; c++) acc[mg][ng][c] = 0.f;

#pragma unroll
    for (int p = 0; p < 3; p++) {
        uint32_t aoff = sbase + ((p == 2) ? 16384u : 0u);
        uint32_t boff = sbase + 32768u + ((p == 1) ? 16384u : 0u);
#pragma unroll
        for (int k0 = 0; k0 < 4; k0++) {
            uint32_t kb = (uint32_t)k0*32 + cb16;
            uint32_t a[2][4];
#pragma unroll
            for (int mg = 0; mg < 2; mg++)
                ldsm_x4(a[mg][0], a[mg][1], a[mg][2], a[mg][3],
                        aoff + SW128((uint32_t)(wm*32 + mg*16 + r8)*128 + kb));
            uint32_t bf[8];
#pragma unroll
            for (int bg = 0; bg < 2; bg++) {
                uint32_t r0, r1, r2, r3;
                ldsm_x4(r0, r1, r2, r3,
                        boff + SW128((uint32_t)(wn*32 + bg*16 + r8)*128 + kb));
                bf[4*bg + 0] = r0; bf[4*bg + 1] = r2;
                bf[4*bg + 2] = r1; bf[4*bg + 3] = r3;
            }
#pragma unroll
            for (int mg = 0; mg < 2; mg++)
#pragma unroll
                for (int ng = 0; ng < 4; ng++)
                    mma_16816(acc[mg][ng], a[mg], bf[2*ng], bf[2*ng + 1]);
        }
    }

#pragma unroll
    for (int mg = 0; mg < 2; mg++) {
        int row = qt*128 + wm*32 + mg*16 + (lane >> 2);
#pragma unroll
        for (int ng = 0; ng < 4; ng++) {
            int col = kt*128 + wn*32 + ng*8 + 2*(lane & 3);
            float2 v0 = make_float2(acc[mg][ng][0]*SCALE, acc[mg][ng][1]*SCALE);
            float2 v1 = make_float2(acc[mg][ng][2]*SCALE, acc[mg][ng][3]*SCALE);
            *(float2*)&out[off + ((size_t)bh*SD + row    )*SD + col] = v0;
            *(float2*)&out[off + ((size_t)bh*SD + row + 8)*SD + col] = v1;
        }
    }
}

// ---------------- 6) binary attention scores + probs + context ---------------
__global__ __launch_bounds__(256)
void attn_ctx_kernel(const float* __restrict__ mask, float* __restrict__ out) {
    __shared__ unsigned long long skb[512];
    __shared__ unsigned long long svt[512];
    __shared__ unsigned long long sqb[64];
    __shared__ unsigned spos[64][16];
    __shared__ unsigned szero[64][16];

    int tid = threadIdx.x;
    int qt = blockIdx.x, bh = blockIdx.y;
    int b = bh / NHD, h = bh % NHD;
    int q0 = qt * 64;

    skb[tid]       = d_kb[(size_t)bh*SD + tid];
    skb[tid + 256] = d_kb[(size_t)bh*SD + tid + 256];
    svt[tid]       = d_vt[(size_t)bh*512 + tid];
    svt[tid + 256] = d_vt[(size_t)bh*512 + tid + 256];
    if (tid < 64) sqb[tid] = d_qb[(size_t)bh*SD + q0 + tid];
    __syncthreads();

    int warp = tid / 32, lane = tid % 32;
    int k1 = warp*32 + lane;
    int k2 = k1 + 256;
    unsigned long long kb1 = skb[k1], kb2 = skb[k2];
    float mk1 = mask[(size_t)b*SD + k1];
    float mk2 = mask[(size_t)b*SD + k2];
    float* attn_base = out + OFF_ATTN + ((size_t)bh*SD + q0)*SD;

    for (int q = 0; q < 64; q++) {
        unsigned long long qw = sqb[q];
        int s1 = 64 - 2*__popcll(qw ^ kb1);
        int s2 = 64 - 2*__popcll(qw ^ kb2);
        float f1 = (float)s1 * SCALE + mk1;
        float f2 = (float)s2 * SCALE + mk2;
        attn_base[(size_t)q*SD + k1] = f1;
        attn_base[(size_t)q*SD + k2] = f2;
        unsigned p1 = __ballot_sync(0xffffffffu, f1 > 0.f);
        unsigned z1 = __ballot_sync(0xffffffffu, f1 == 0.f);
        unsigned p2 = __ballot_sync(0xffffffffu, f2 > 0.f);
        unsigned z2 = __ballot_sync(0xffffffffu, f2 == 0.f);
        if (lane == 0) {
            spos[q][warp]      = p1;  spos[q][warp + 8]  = p2;
            szero[q][warp]     = z1;  szero[q][warp + 8] = z2;
        }
    }
    __syncthreads();

    int q  = tid / 4;
    int dg = tid % 4;
    float tmp[16];
#pragma unroll
    for (int dd = 0; dd < 16; dd++) {
        int d = dg*16 + dd;
        const unsigned* v32 = (const unsigned*)&svt[d*8];
        int ip = 0, iz = 0;
#pragma unroll
        for (int w16 = 0; w16 < 16; w16++) {
            unsigned V1 = v32[w16];
            unsigned P  = spos[q][w16];
            unsigned Z  = szero[q][w16];
            ip += 2*__popc(P & V1) - __popc(P);
            iz += 2*__popc(Z & V1) - __popc(Z);
        }
        tmp[dd] = (float)ip + 0.5f*(float)iz;
    }
    float* cbase = out + OFF_CTX + ((size_t)(b*SD + q0 + q))*HD + h*HSD + dg*16;
#pragma unroll
    for (int i = 0; i < 4; i++) {
        float4 ov; ov.x = tmp[4*i]; ov.y = tmp[4*i+1]; ov.z = tmp[4*i+2]; ov.w = tmp[4*i+3];
        *(float4*)(cbase + 4*i) = ov;
    }
}

// ------------------------------- launch --------------------------------------
extern "C" void kernel_launch(void* const* d_in, const int* in_sizes, int n_in,
                              void* d_out, int out_size) {
    const float* X    = (const float*)d_in[0];
    const float* mask = (const float*)d_in[1];
    const float* Wq   = (const float*)d_in[2];
    const float* bq   = (const float*)d_in[3];
    const float* Wk   = (const float*)d_in[4];
    const float* bk   = (const float*)d_in[5];
    const float* Wv   = (const float*)d_in[6];
    const float* bv   = (const float*)d_in[7];
    float* out = (float*)d_out;

    static int smem_set = 0;
    if (!smem_set) {
        cudaFuncSetAttribute(score_mma_kernel,
                             cudaFuncAttributeMaxDynamicSharedMemorySize, SC_SMEM);
        cudaFuncSetAttribute(proj_mma_kernel,
                             cudaFuncAttributeMaxDynamicSharedMemorySize, PJ_SMEM);
        smem_set = 1;
    }

    scale_kernel<<<dim3(HD, 3), 32>>>(Wq, Wk, Wv);
    xsplit_kernel<<<(MROWS*HD)/(256*4), 256>>>(X);
    wsplit_kernel<<<dim3((HD*HD)/(256*4), 3), 256>>>(Wq, Wk, Wv);
    proj_mma_kernel<<<dim3(18, 64), 512, PJ_SMEM>>>(bq, bk, bv);
    fix_kernel<<<64, 256>>>(X, Wq, Wk, Wv, bq, bk, bv);
    pack_qk_kernel<<<(2*BH*SD)/8, 256>>>();
    pack_vt_kernel<<<dim3(8, BH), 256>>>();
    score_mma_kernel<<<dim3(16, BH, 3), 512, SC_SMEM>>>(out);
    attn_ctx_kernel<<<dim3(8, BH), 256>>>(mask, out);
}